// round 2
// baseline (speedup 1.0000x reference)
#include <cuda_runtime.h>

#define Bn   16
#define Cn   64
#define Hn   256
#define Wn   256
#define OHW  125
#define TOH  16
#define TOW  64

typedef unsigned long long u64;

// Persistent scratch (device globals are allowed; allocation APIs are not)
__device__ float  g_weight[Bn * Cn * 64 * 16];   // [b][c][tap=ki*8+kj][nn]  (4 MB)
__device__ float  g_s[Bn * Hn * Wn];             // channel sum of squares   (4 MB)
__device__ float  g_norm[Bn * OHW * OHW];        // box-summed norm          (1 MB)
__device__ double g_part1[1024];                 // deterministic partials
__device__ double g_part2[1024];
__device__ float  g_stdadd;                      // std/10 + 1e-9

__constant__ float cs8[8] = {1.f,  0.70710678118654752f, 0.f, -0.70710678118654752f,
                             -1.f, -0.70710678118654752f, 0.f,  0.70710678118654752f};
__constant__ float sn8[8] = {0.f,  0.70710678118654752f, 1.f,  0.70710678118654752f,
                             0.f, -0.70710678118654752f, -1.f, -0.70710678118654752f};

__device__ __forceinline__ u64 pack2(float lo, float hi) {
    u64 r; asm("mov.b64 %0, {%1, %2};" : "=l"(r) : "f"(lo), "f"(hi)); return r;
}
__device__ __forceinline__ void unpack2(float& lo, float& hi, u64 v) {
    asm("mov.b64 {%0, %1}, %2;" : "=f"(lo), "=f"(hi) : "l"(v));
}
__device__ __forceinline__ void ffma2(u64& d, u64 a, u64 b) {
    asm("fma.rn.f32x2 %0, %1, %2, %0;" : "+l"(d) : "l"(a), "l"(b));
}

// ---------------------------------------------------------------------------
// K1: weight generation (rfft2 -> coeff scale -> irfft2, ortho, 8x8 DFT tables)
// ---------------------------------------------------------------------------
__global__ void wgen_kernel(const float* __restrict__ z, const float* __restrict__ fc) {
    int bid = blockIdx.x;            // 16384 = 16 * 16 * 64
    int b   = bid >> 10;
    int rest = bid & 1023;
    int nn  = rest >> 6;             // ni*4 + nj
    int c   = rest & 63;
    int ni  = nn >> 2, nj = nn & 3;

    __shared__ float w[64];
    __shared__ float Fr[8][5], Fi[8][5];

    int t = threadIdx.x;
    int i = t >> 3, j = t & 7;
    w[t] = z[((b * Cn + c) * 32 + ni * 8 + i) * 32 + (nj * 8 + j)];
    __syncthreads();

    if (t < 40) {
        int u = t / 5, v = t % 5;
        float sr = 0.f, si = 0.f;
        for (int ii = 0; ii < 8; ii++)
            for (int jj = 0; jj < 8; jj++) {
                int m = (u * ii + v * jj) & 7;
                float wv = w[ii * 8 + jj];
                sr += wv * cs8[m];      // e^{-i th} = cos - i sin
                si -= wv * sn8[m];
            }
        sr *= 0.125f; si *= 0.125f;     // ortho forward: 1/sqrt(64)
        Fr[u][v] = sr * fc[(u * 5 + v) * 2 + 0];
        Fi[u][v] = si * fc[(u * 5 + v) * 2 + 1];
    }
    __syncthreads();

    float acc = 0.f;
    #pragma unroll
    for (int v = 0; v <= 4; v++) {
        float gr = 0.f, gi = 0.f;
        #pragma unroll
        for (int u = 0; u < 8; u++) {
            int m = (u * i) & 7;        // e^{+i th}
            gr += Fr[u][v] * cs8[m] - Fi[u][v] * sn8[m];
            gi += Fr[u][v] * sn8[m] + Fi[u][v] * cs8[m];
        }
        if (v == 0)       acc += gr;
        else if (v == 4)  acc += (j & 1) ? -gr : gr;
        else {
            int m = (v * j) & 7;
            acc += 2.f * (gr * cs8[m] - gi * sn8[m]);
        }
    }
    acc *= 0.125f;
    g_weight[((b * Cn + c) * 64 + i * 8 + j) * 16 + nn] = acc;
}

// ---------------------------------------------------------------------------
// K2: s[b,h,w] = sum_c x[b,c,h,w]^2
// ---------------------------------------------------------------------------
__global__ void sumsq_kernel(const float* __restrict__ x) {
    int idx = blockIdx.x * 256 + threadIdx.x;      // 1,048,576 threads
    int b  = idx >> 16;
    int hw = idx & 65535;
    const float* xp = x + (size_t)b * Cn * Hn * Wn + hw;
    float s = 0.f;
    #pragma unroll
    for (int c = 0; c < Cn; c++) {
        float v = xp[c * Hn * Wn];
        s += v * v;
    }
    g_s[idx] = s;
}

// ---------------------------------------------------------------------------
// K3: norm = 8x8 stride-2 box sum of s; deterministic double partials
// ---------------------------------------------------------------------------
__global__ void boxnorm_kernel() {
    int idx = blockIdx.x * 256 + threadIdx.x;
    bool valid = idx < Bn * OHW * OHW;
    float acc = 0.f;
    if (valid) {
        int b  = idx / (OHW * OHW);
        int r  = idx % (OHW * OHW);
        int oh = r / OHW, ow = r % OHW;
        const float* sp = g_s + b * Hn * Wn + (2 * oh) * Wn + 2 * ow;
        #pragma unroll
        for (int ki = 0; ki < 8; ki++)
            #pragma unroll
            for (int kj = 0; kj < 8; kj++)
                acc += sp[ki * Wn + kj];
        g_norm[idx] = acc;
    }
    __shared__ double s1[256], s2[256];
    s1[threadIdx.x] = valid ? (double)acc : 0.0;
    s2[threadIdx.x] = valid ? (double)acc * (double)acc : 0.0;
    __syncthreads();
    for (int st = 128; st > 0; st >>= 1) {
        if (threadIdx.x < st) {
            s1[threadIdx.x] += s1[threadIdx.x + st];
            s2[threadIdx.x] += s2[threadIdx.x + st];
        }
        __syncthreads();
    }
    if (threadIdx.x == 0) {
        g_part1[blockIdx.x] = s1[0];
        g_part2[blockIdx.x] = s2[0];
    }
}

// ---------------------------------------------------------------------------
// K4: finalize ddof=1 std
// ---------------------------------------------------------------------------
__global__ void stats_kernel() {
    __shared__ double s1[256], s2[256];
    double a = 0.0, b2 = 0.0;
    for (int i = threadIdx.x; i < 1024; i += 256) { a += g_part1[i]; b2 += g_part2[i]; }
    s1[threadIdx.x] = a; s2[threadIdx.x] = b2;
    __syncthreads();
    for (int st = 128; st > 0; st >>= 1) {
        if (threadIdx.x < st) {
            s1[threadIdx.x] += s1[threadIdx.x + st];
            s2[threadIdx.x] += s2[threadIdx.x + st];
        }
        __syncthreads();
    }
    if (threadIdx.x == 0) {
        double S1 = s1[0] * 16.0;           // each unique value appears 16x
        double S2 = s2[0] * 16.0;
        double Nt = 4000000.0;              // 256 * 125 * 125
        double var = (S2 - S1 * S1 / Nt) / (Nt - 1.0);
        g_stdadd = (float)(sqrt(var) * 0.1 + 1e-9);
    }
}

// ---------------------------------------------------------------------------
// K5: main grouped conv, packed fp32x2 FMA.
// Block = (group b, 16 oh x 64 ow tile). 256 threads.
// x tile parity-split by column (conflict-free stride-2 taps); weights stored
// duplicated as float2 so each tap weight is one LDS.64; accumulators packed
// over the two ow half-tiles -> fma.rn.f32x2 (2 FMA / instr).
// ---------------------------------------------------------------------------
__global__ void __launch_bounds__(256, 2) conv_kernel(const float* __restrict__ x,
                                                      float* __restrict__ out) {
    int b   = blockIdx.z;
    int oh0 = blockIdx.y * TOH;
    int ow0 = blockIdx.x * TOW;

    __shared__ float  xs[2][38][68];    // [col parity][row][col/2]
    __shared__ float2 ws2[64][16];      // [tap][nn], duplicated weight

    int tid  = threadIdx.x;
    int warp = tid >> 5, lane = tid & 31;

    u64 acc2[16][2];
    #pragma unroll
    for (int n = 0; n < 16; n++) {
        acc2[n][0] = 0ull;
        acc2[n][1] = 0ull;
    }

    int ih0 = 2 * oh0, iw0 = 2 * ow0;
    const float* xb = x + (size_t)b * Cn * Hn * Wn;

    for (int c = 0; c < Cn; c++) {
        __syncthreads();
        const float* xc = xb + (size_t)c * Hn * Wn;
        for (int li = tid; li < 38 * 134; li += 256) {
            int r  = li / 134, cc = li % 134;
            int ih = ih0 + r,  iw = iw0 + cc;
            float v = (ih < Hn && iw < Wn) ? xc[ih * Wn + iw] : 0.f;
            xs[cc & 1][r][cc >> 1] = v;
        }
        const float* wp = g_weight + ((size_t)b * Cn + c) * 64 * 16;
        for (int li = tid; li < 1024; li += 256) {
            float wv = wp[li];
            ws2[li >> 4][li & 15] = make_float2(wv, wv);
        }
        __syncthreads();

        #pragma unroll 1
        for (int ki = 0; ki < 8; ki++) {
            int r0 = 2 * warp + ki;
            int r1 = 2 * (warp + 8) + ki;
            #pragma unroll
            for (int kj = 0; kj < 8; kj++) {
                int par = kj & 1, off = kj >> 1;
                u64 xa = pack2(xs[par][r0][lane + off], xs[par][r0][lane + 32 + off]);
                u64 xb2 = pack2(xs[par][r1][lane + off], xs[par][r1][lane + 32 + off]);
                const u64* wrow = (const u64*)ws2[ki * 8 + kj];
                #pragma unroll
                for (int n = 0; n < 16; n++) {
                    u64 wn = wrow[n];          // LDS.64, broadcast
                    ffma2(acc2[n][0], wn, xa);
                    ffma2(acc2[n][1], wn, xb2);
                }
            }
        }
    }

    float stdadd = g_stdadd;
    #pragma unroll
    for (int op = 0; op < 2; op++) {
        int oh = oh0 + warp + 8 * op;
        if (oh >= OHW) continue;
        #pragma unroll
        for (int oq = 0; oq < 2; oq++) {
            int ow = ow0 + lane + 32 * oq;
            if (ow >= OHW) continue;
            float nrm = g_norm[b * OHW * OHW + oh * OHW + ow];
            float fac = 0.01f / sqrtf(nrm + stdadd);
            #pragma unroll
            for (int n = 0; n < 16; n++) {
                float lo, hi;
                unpack2(lo, hi, acc2[n][op]);
                float v = (oq == 0) ? lo : hi;
                out[(((size_t)b * 16 + n) * OHW + oh) * OHW + ow] = v * fac;
            }
        }
    }
}

extern "C" void kernel_launch(void* const* d_in, const int* in_sizes, int n_in,
                              void* d_out, int out_size) {
    const float* x  = (const float*)d_in[0];   // [16,64,256,256]
    const float* z  = (const float*)d_in[1];   // [16,64,32,32]
    const float* fc = (const float*)d_in[2];   // [8,5,2]
    float* out = (float*)d_out;                // [16,16,125,125]

    wgen_kernel<<<16384, 64>>>(z, fc);
    sumsq_kernel<<<4096, 256>>>(x);
    boxnorm_kernel<<<(Bn * OHW * OHW + 255) / 256, 256>>>();
    stats_kernel<<<1, 256>>>();
    conv_kernel<<<dim3(2, 8, Bn), 256>>>(x, out);
}

// round 3
// speedup vs baseline: 1.2050x; 1.2050x over previous
#include <cuda_runtime.h>

#define Bn   16
#define Cn   64
#define Hn   256
#define Wn   256
#define OHW  125
#define TOH  16
#define TOW  64

typedef unsigned long long u64;

// Persistent scratch (device globals are allowed; allocation APIs are not)
__device__ float  g_weight[Bn * Cn * 64 * 16];   // [b][c][tap=ki*8+kj][nn]  (4 MB)
__device__ float  g_s[Bn * Hn * Wn];             // channel sum of squares   (4 MB)
__device__ float  g_norm[Bn * OHW * OHW];        // box-summed norm          (1 MB)
__device__ double g_part1[1024];                 // deterministic partials
__device__ double g_part2[1024];
__device__ float  g_stdadd;                      // std/10 + 1e-9

__constant__ float cs8[8] = {1.f,  0.70710678118654752f, 0.f, -0.70710678118654752f,
                             -1.f, -0.70710678118654752f, 0.f,  0.70710678118654752f};
__constant__ float sn8[8] = {0.f,  0.70710678118654752f, 1.f,  0.70710678118654752f,
                             0.f, -0.70710678118654752f, -1.f, -0.70710678118654752f};

__device__ __forceinline__ u64 pack2(float lo, float hi) {
    u64 r; asm("mov.b64 %0, {%1, %2};" : "=l"(r) : "f"(lo), "f"(hi)); return r;
}
__device__ __forceinline__ void unpack2(float& lo, float& hi, u64 v) {
    asm("mov.b64 {%0, %1}, %2;" : "=f"(lo), "=f"(hi) : "l"(v));
}
__device__ __forceinline__ void ffma2(u64& d, u64 a, u64 b) {
    asm("fma.rn.f32x2 %0, %1, %2, %0;" : "+l"(d) : "l"(a), "l"(b));
}

// ---------------------------------------------------------------------------
// K1: weight generation (rfft2 -> coeff scale -> irfft2, ortho, 8x8 DFT tables)
// ---------------------------------------------------------------------------
__global__ void wgen_kernel(const float* __restrict__ z, const float* __restrict__ fc) {
    int bid = blockIdx.x;            // 16384 = 16 * 16 * 64
    int b   = bid >> 10;
    int rest = bid & 1023;
    int nn  = rest >> 6;             // ni*4 + nj
    int c   = rest & 63;
    int ni  = nn >> 2, nj = nn & 3;

    __shared__ float w[64];
    __shared__ float Fr[8][5], Fi[8][5];

    int t = threadIdx.x;
    int i = t >> 3, j = t & 7;
    w[t] = z[((b * Cn + c) * 32 + ni * 8 + i) * 32 + (nj * 8 + j)];
    __syncthreads();

    if (t < 40) {
        int u = t / 5, v = t % 5;
        float sr = 0.f, si = 0.f;
        for (int ii = 0; ii < 8; ii++)
            for (int jj = 0; jj < 8; jj++) {
                int m = (u * ii + v * jj) & 7;
                float wv = w[ii * 8 + jj];
                sr += wv * cs8[m];      // e^{-i th} = cos - i sin
                si -= wv * sn8[m];
            }
        sr *= 0.125f; si *= 0.125f;     // ortho forward: 1/sqrt(64)
        Fr[u][v] = sr * fc[(u * 5 + v) * 2 + 0];
        Fi[u][v] = si * fc[(u * 5 + v) * 2 + 1];
    }
    __syncthreads();

    float acc = 0.f;
    #pragma unroll
    for (int v = 0; v <= 4; v++) {
        float gr = 0.f, gi = 0.f;
        #pragma unroll
        for (int u = 0; u < 8; u++) {
            int m = (u * i) & 7;        // e^{+i th}
            gr += Fr[u][v] * cs8[m] - Fi[u][v] * sn8[m];
            gi += Fr[u][v] * sn8[m] + Fi[u][v] * cs8[m];
        }
        if (v == 0)       acc += gr;
        else if (v == 4)  acc += (j & 1) ? -gr : gr;
        else {
            int m = (v * j) & 7;
            acc += 2.f * (gr * cs8[m] - gi * sn8[m]);
        }
    }
    acc *= 0.125f;
    g_weight[((b * Cn + c) * 64 + i * 8 + j) * 16 + nn] = acc;
}

// ---------------------------------------------------------------------------
// K2: s[b,h,w] = sum_c x[b,c,h,w]^2
// ---------------------------------------------------------------------------
__global__ void sumsq_kernel(const float* __restrict__ x) {
    int idx = blockIdx.x * 256 + threadIdx.x;      // 1,048,576 threads
    int b  = idx >> 16;
    int hw = idx & 65535;
    const float* xp = x + (size_t)b * Cn * Hn * Wn + hw;
    float s = 0.f;
    #pragma unroll
    for (int c = 0; c < Cn; c++) {
        float v = xp[c * Hn * Wn];
        s += v * v;
    }
    g_s[idx] = s;
}

// ---------------------------------------------------------------------------
// K3: norm = 8x8 stride-2 box sum of s; deterministic double partials
// ---------------------------------------------------------------------------
__global__ void boxnorm_kernel() {
    int idx = blockIdx.x * 256 + threadIdx.x;
    bool valid = idx < Bn * OHW * OHW;
    float acc = 0.f;
    if (valid) {
        int b  = idx / (OHW * OHW);
        int r  = idx % (OHW * OHW);
        int oh = r / OHW, ow = r % OHW;
        const float* sp = g_s + b * Hn * Wn + (2 * oh) * Wn + 2 * ow;
        #pragma unroll
        for (int ki = 0; ki < 8; ki++)
            #pragma unroll
            for (int kj = 0; kj < 8; kj++)
                acc += sp[ki * Wn + kj];
        g_norm[idx] = acc;
    }
    __shared__ double s1[256], s2[256];
    s1[threadIdx.x] = valid ? (double)acc : 0.0;
    s2[threadIdx.x] = valid ? (double)acc * (double)acc : 0.0;
    __syncthreads();
    for (int st = 128; st > 0; st >>= 1) {
        if (threadIdx.x < st) {
            s1[threadIdx.x] += s1[threadIdx.x + st];
            s2[threadIdx.x] += s2[threadIdx.x + st];
        }
        __syncthreads();
    }
    if (threadIdx.x == 0) {
        g_part1[blockIdx.x] = s1[0];
        g_part2[blockIdx.x] = s2[0];
    }
}

// ---------------------------------------------------------------------------
// K4: main grouped conv (now launched 4th so ncu captures it).
// Packed fp32x2 FMA along the nn axis: weight pairs are natural contiguous
// LDS.64 with pair-aligned dests; x duplicated into both lanes; 32 u64 accs.
// Writes UNNORMALIZED response; scale_kernel applies norm afterward.
// ---------------------------------------------------------------------------
__global__ void __launch_bounds__(256, 2) conv_kernel(const float* __restrict__ x,
                                                      float* __restrict__ out) {
    int b   = blockIdx.z;
    int oh0 = blockIdx.y * TOH;
    int ow0 = blockIdx.x * TOW;

    __shared__ float xs[2][38][68];     // [col parity][row][col/2]
    __shared__ u64   ws2[64 * 8];       // [tap][nn-pair]

    int tid  = threadIdx.x;
    int warp = tid >> 5, lane = tid & 31;

    u64 acc2[8][2][2];                  // [nn-pair][oh-half][ow-half]
    #pragma unroll
    for (int m = 0; m < 8; m++)
        #pragma unroll
        for (int p = 0; p < 2; p++)
            #pragma unroll
            for (int q = 0; q < 2; q++) acc2[m][p][q] = 0ull;

    int ih0 = 2 * oh0, iw0 = 2 * ow0;
    const float* xb = x + (size_t)b * Cn * Hn * Wn;

    for (int c = 0; c < Cn; c++) {
        __syncthreads();
        const float* xc = xb + (size_t)c * Hn * Wn;
        for (int li = tid; li < 38 * 134; li += 256) {
            int r  = li / 134, cc = li % 134;
            int ih = ih0 + r,  iw = iw0 + cc;
            float v = (ih < Hn && iw < Wn) ? xc[ih * Wn + iw] : 0.f;
            xs[cc & 1][r][cc >> 1] = v;
        }
        const u64* wp = (const u64*)(g_weight + ((size_t)b * Cn + c) * 64 * 16);
        for (int li = tid; li < 512; li += 256) ws2[li] = wp[li];
        __syncthreads();

        #pragma unroll 1
        for (int ki = 0; ki < 8; ki++) {
            int r0 = 2 * warp + ki;
            int r1 = 2 * (warp + 8) + ki;
            #pragma unroll
            for (int kj = 0; kj < 8; kj++) {
                int par = kj & 1, off = kj >> 1;
                float x00 = xs[par][r0][lane + off];
                float x01 = xs[par][r0][lane + 32 + off];
                float x10 = xs[par][r1][lane + off];
                float x11 = xs[par][r1][lane + 32 + off];
                u64 d00 = pack2(x00, x00);
                u64 d01 = pack2(x01, x01);
                u64 d10 = pack2(x10, x10);
                u64 d11 = pack2(x11, x11);
                const u64* wrow = ws2 + (ki * 8 + kj) * 8;
                #pragma unroll
                for (int m = 0; m < 8; m++) {
                    u64 wm = wrow[m];          // LDS.64, broadcast, pair-aligned
                    ffma2(acc2[m][0][0], wm, d00);
                    ffma2(acc2[m][0][1], wm, d01);
                    ffma2(acc2[m][1][0], wm, d10);
                    ffma2(acc2[m][1][1], wm, d11);
                }
            }
        }
    }

    #pragma unroll
    for (int op = 0; op < 2; op++) {
        int oh = oh0 + warp + 8 * op;
        if (oh >= OHW) continue;
        #pragma unroll
        for (int oq = 0; oq < 2; oq++) {
            int ow = ow0 + lane + 32 * oq;
            if (ow >= OHW) continue;
            #pragma unroll
            for (int m = 0; m < 8; m++) {
                float lo, hi;
                unpack2(lo, hi, acc2[m][op][oq]);
                out[(((size_t)b * 16 + 2 * m) * OHW + oh) * OHW + ow]     = lo;
                out[(((size_t)b * 16 + 2 * m + 1) * OHW + oh) * OHW + ow] = hi;
            }
        }
    }
}

// ---------------------------------------------------------------------------
// K5: finalize ddof=1 std
// ---------------------------------------------------------------------------
__global__ void stats_kernel() {
    __shared__ double s1[256], s2[256];
    double a = 0.0, b2 = 0.0;
    for (int i = threadIdx.x; i < 1024; i += 256) { a += g_part1[i]; b2 += g_part2[i]; }
    s1[threadIdx.x] = a; s2[threadIdx.x] = b2;
    __syncthreads();
    for (int st = 128; st > 0; st >>= 1) {
        if (threadIdx.x < st) {
            s1[threadIdx.x] += s1[threadIdx.x + st];
            s2[threadIdx.x] += s2[threadIdx.x + st];
        }
        __syncthreads();
    }
    if (threadIdx.x == 0) {
        double S1 = s1[0] * 16.0;           // each unique value appears 16x
        double S2 = s2[0] * 16.0;
        double Nt = 4000000.0;              // 256 * 125 * 125
        double var = (S2 - S1 * S1 / Nt) / (Nt - 1.0);
        g_stdadd = (float)(sqrt(var) * 0.1 + 1e-9);
    }
}

// ---------------------------------------------------------------------------
// K6: apply normalization: out *= 0.01 / sqrt(norm + stdadd)
// ---------------------------------------------------------------------------
__global__ void scale_kernel(float* __restrict__ out) {
    int idx = blockIdx.x * 256 + threadIdx.x;
    if (idx >= Bn * 16 * OHW * OHW) return;
    int per_b = 16 * OHW * OHW;
    int b = idx / per_b;
    int p = idx % (OHW * OHW);
    float nrm = g_norm[b * OHW * OHW + p];
    out[idx] *= 0.01f * rsqrtf(nrm + g_stdadd);
}

extern "C" void kernel_launch(void* const* d_in, const int* in_sizes, int n_in,
                              void* d_out, int out_size) {
    const float* x  = (const float*)d_in[0];   // [16,64,256,256]
    const float* z  = (const float*)d_in[1];   // [16,64,32,32]
    const float* fc = (const float*)d_in[2];   // [8,5,2]
    float* out = (float*)d_out;                // [16,16,125,125]

    wgen_kernel<<<16384, 64>>>(z, fc);
    sumsq_kernel<<<4096, 256>>>(x);
    boxnorm_kernel<<<(Bn * OHW * OHW + 255) / 256, 256>>>();
    conv_kernel<<<dim3(2, 8, Bn), 256>>>(x, out);   // 4th launch -> profiled slot
    stats_kernel<<<1, 256>>>();
    scale_kernel<<<(Bn * 16 * OHW * OHW + 255) / 256, 256>>>(out);
}

// round 4
// speedup vs baseline: 1.2622x; 1.0474x over previous
#include <cuda_runtime.h>

#define Bn   16
#define Cn   64
#define Hn   256
#define Wn   256
#define OHW  125
#define TOH  8
#define TOW  64

typedef unsigned long long u64;

// Persistent scratch (device globals are allowed; allocation APIs are not)
__device__ float  g_weight[Bn * Cn * 64 * 16];   // [b][c][tap=ki*8+kj][nn]  (4 MB)
__device__ float  g_s[Bn * Hn * Wn];             // channel sum of squares   (4 MB)
__device__ float  g_norm[Bn * OHW * OHW];        // box-summed norm          (1 MB)
__device__ double g_part1[1024];                 // deterministic partials
__device__ double g_part2[1024];
__device__ float  g_stdadd;                      // std/10 + 1e-9

__constant__ float cs8[8] = {1.f,  0.70710678118654752f, 0.f, -0.70710678118654752f,
                             -1.f, -0.70710678118654752f, 0.f,  0.70710678118654752f};
__constant__ float sn8[8] = {0.f,  0.70710678118654752f, 1.f,  0.70710678118654752f,
                             0.f, -0.70710678118654752f, -1.f, -0.70710678118654752f};

__device__ __forceinline__ u64 pack2(float lo, float hi) {
    u64 r; asm("mov.b64 %0, {%1, %2};" : "=l"(r) : "f"(lo), "f"(hi)); return r;
}
__device__ __forceinline__ void unpack2(float& lo, float& hi, u64 v) {
    asm("mov.b64 {%0, %1}, %2;" : "=f"(lo), "=f"(hi) : "l"(v));
}
__device__ __forceinline__ void ffma2(u64& d, u64 a, u64 b) {
    asm("fma.rn.f32x2 %0, %1, %2, %0;" : "+l"(d) : "l"(a), "l"(b));
}

// ---------------------------------------------------------------------------
// K1: weight generation (rfft2 -> coeff scale -> irfft2, ortho, 8x8 DFT tables)
// ---------------------------------------------------------------------------
__global__ void wgen_kernel(const float* __restrict__ z, const float* __restrict__ fc) {
    int bid = blockIdx.x;            // 16384 = 16 * 16 * 64
    int b   = bid >> 10;
    int rest = bid & 1023;
    int nn  = rest >> 6;             // ni*4 + nj
    int c   = rest & 63;
    int ni  = nn >> 2, nj = nn & 3;

    __shared__ float w[64];
    __shared__ float Fr[8][5], Fi[8][5];

    int t = threadIdx.x;
    int i = t >> 3, j = t & 7;
    w[t] = z[((b * Cn + c) * 32 + ni * 8 + i) * 32 + (nj * 8 + j)];
    __syncthreads();

    if (t < 40) {
        int u = t / 5, v = t % 5;
        float sr = 0.f, si = 0.f;
        for (int ii = 0; ii < 8; ii++)
            for (int jj = 0; jj < 8; jj++) {
                int m = (u * ii + v * jj) & 7;
                float wv = w[ii * 8 + jj];
                sr += wv * cs8[m];      // e^{-i th} = cos - i sin
                si -= wv * sn8[m];
            }
        sr *= 0.125f; si *= 0.125f;     // ortho forward: 1/sqrt(64)
        Fr[u][v] = sr * fc[(u * 5 + v) * 2 + 0];
        Fi[u][v] = si * fc[(u * 5 + v) * 2 + 1];
    }
    __syncthreads();

    float acc = 0.f;
    #pragma unroll
    for (int v = 0; v <= 4; v++) {
        float gr = 0.f, gi = 0.f;
        #pragma unroll
        for (int u = 0; u < 8; u++) {
            int m = (u * i) & 7;        // e^{+i th}
            gr += Fr[u][v] * cs8[m] - Fi[u][v] * sn8[m];
            gi += Fr[u][v] * sn8[m] + Fi[u][v] * cs8[m];
        }
        if (v == 0)       acc += gr;
        else if (v == 4)  acc += (j & 1) ? -gr : gr;
        else {
            int m = (v * j) & 7;
            acc += 2.f * (gr * cs8[m] - gi * sn8[m]);
        }
    }
    acc *= 0.125f;
    g_weight[((b * Cn + c) * 64 + i * 8 + j) * 16 + nn] = acc;
}

// ---------------------------------------------------------------------------
// K2: s[b,h,w] = sum_c x[b,c,h,w]^2
// ---------------------------------------------------------------------------
__global__ void sumsq_kernel(const float* __restrict__ x) {
    int idx = blockIdx.x * 256 + threadIdx.x;      // 1,048,576 threads
    int b  = idx >> 16;
    int hw = idx & 65535;
    const float* xp = x + (size_t)b * Cn * Hn * Wn + hw;
    float s = 0.f;
    #pragma unroll
    for (int c = 0; c < Cn; c++) {
        float v = xp[c * Hn * Wn];
        s += v * v;
    }
    g_s[idx] = s;
}

// ---------------------------------------------------------------------------
// K3: norm = 8x8 stride-2 box sum of s; deterministic double partials
// ---------------------------------------------------------------------------
__global__ void boxnorm_kernel() {
    int idx = blockIdx.x * 256 + threadIdx.x;
    bool valid = idx < Bn * OHW * OHW;
    float acc = 0.f;
    if (valid) {
        int b  = idx / (OHW * OHW);
        int r  = idx % (OHW * OHW);
        int oh = r / OHW, ow = r % OHW;
        const float* sp = g_s + b * Hn * Wn + (2 * oh) * Wn + 2 * ow;
        #pragma unroll
        for (int ki = 0; ki < 8; ki++)
            #pragma unroll
            for (int kj = 0; kj < 8; kj++)
                acc += sp[ki * Wn + kj];
        g_norm[idx] = acc;
    }
    __shared__ double s1[256], s2[256];
    s1[threadIdx.x] = valid ? (double)acc : 0.0;
    s2[threadIdx.x] = valid ? (double)acc * (double)acc : 0.0;
    __syncthreads();
    for (int st = 128; st > 0; st >>= 1) {
        if (threadIdx.x < st) {
            s1[threadIdx.x] += s1[threadIdx.x + st];
            s2[threadIdx.x] += s2[threadIdx.x + st];
        }
        __syncthreads();
    }
    if (threadIdx.x == 0) {
        g_part1[blockIdx.x] = s1[0];
        g_part2[blockIdx.x] = s2[0];
    }
}

// ---------------------------------------------------------------------------
// K4: main grouped conv (4th launch -> profiled slot).
// Tile 8oh x 64ow per block, one oh row per warp. acc[8 nn-pair][2 ow-half]
// = 16 u64 = 32 regs -> 3+ CTAs/SM. Packed fp32x2 FMA along the nn axis.
// Writes UNNORMALIZED response; scale_kernel applies norm afterward.
// ---------------------------------------------------------------------------
__global__ void __launch_bounds__(256, 3) conv_kernel(const float* __restrict__ x,
                                                      float* __restrict__ out) {
    int b   = blockIdx.z;
    int oh0 = blockIdx.y * TOH;
    int ow0 = blockIdx.x * TOW;

    __shared__ float xs[2][22][68];     // [col parity][row][col/2]  (~11.9 KB)
    __shared__ u64   ws2[64 * 8];       // [tap][nn-pair]            (4 KB)

    int tid  = threadIdx.x;
    int warp = tid >> 5, lane = tid & 31;

    u64 acc2[8][2];                     // [nn-pair][ow-half]
    #pragma unroll
    for (int m = 0; m < 8; m++) { acc2[m][0] = 0ull; acc2[m][1] = 0ull; }

    int ih0 = 2 * oh0, iw0 = 2 * ow0;
    const float* xb = x + (size_t)b * Cn * Hn * Wn;

    for (int c = 0; c < Cn; c++) {
        __syncthreads();
        const float* xc = xb + (size_t)c * Hn * Wn;
        #pragma unroll
        for (int k = 0; k < 12; k++) {
            int li = tid + k * 256;
            if (li < 22 * 134) {
                int r  = li / 134, cc = li % 134;
                int ih = ih0 + r,  iw = iw0 + cc;
                float v = (ih < Hn && iw < Wn) ? xc[ih * Wn + iw] : 0.f;
                xs[cc & 1][r][cc >> 1] = v;
            }
        }
        const u64* wp = (const u64*)(g_weight + ((size_t)b * Cn + c) * 64 * 16);
        ws2[tid]       = wp[tid];
        ws2[tid + 256] = wp[tid + 256];
        __syncthreads();

        #pragma unroll 1
        for (int ki = 0; ki < 8; ki++) {
            int r = 2 * warp + ki;
            #pragma unroll
            for (int kj = 0; kj < 8; kj++) {
                int par = kj & 1, off = kj >> 1;
                float x0 = xs[par][r][lane + off];
                float x1 = xs[par][r][lane + 32 + off];
                u64 d0 = pack2(x0, x0);
                u64 d1 = pack2(x1, x1);
                const u64* wrow = ws2 + (ki * 8 + kj) * 8;
                #pragma unroll
                for (int m = 0; m < 8; m++) {
                    u64 wm = wrow[m];          // LDS.64, uniform broadcast
                    ffma2(acc2[m][0], wm, d0);
                    ffma2(acc2[m][1], wm, d1);
                }
            }
        }
    }

    int oh = oh0 + warp;
    if (oh < OHW) {
        #pragma unroll
        for (int oq = 0; oq < 2; oq++) {
            int ow = ow0 + lane + 32 * oq;
            if (ow >= OHW) continue;
            #pragma unroll
            for (int m = 0; m < 8; m++) {
                float lo, hi;
                unpack2(lo, hi, acc2[m][oq]);
                out[(((size_t)b * 16 + 2 * m) * OHW + oh) * OHW + ow]     = lo;
                out[(((size_t)b * 16 + 2 * m + 1) * OHW + oh) * OHW + ow] = hi;
            }
        }
    }
}

// ---------------------------------------------------------------------------
// K5: finalize ddof=1 std
// ---------------------------------------------------------------------------
__global__ void stats_kernel() {
    __shared__ double s1[256], s2[256];
    double a = 0.0, b2 = 0.0;
    for (int i = threadIdx.x; i < 1024; i += 256) { a += g_part1[i]; b2 += g_part2[i]; }
    s1[threadIdx.x] = a; s2[threadIdx.x] = b2;
    __syncthreads();
    for (int st = 128; st > 0; st >>= 1) {
        if (threadIdx.x < st) {
            s1[threadIdx.x] += s1[threadIdx.x + st];
            s2[threadIdx.x] += s2[threadIdx.x + st];
        }
        __syncthreads();
    }
    if (threadIdx.x == 0) {
        double S1 = s1[0] * 16.0;           // each unique value appears 16x
        double S2 = s2[0] * 16.0;
        double Nt = 4000000.0;              // 256 * 125 * 125
        double var = (S2 - S1 * S1 / Nt) / (Nt - 1.0);
        g_stdadd = (float)(sqrt(var) * 0.1 + 1e-9);
    }
}

// ---------------------------------------------------------------------------
// K6: apply normalization: out *= 0.01 / sqrt(norm + stdadd)
// ---------------------------------------------------------------------------
__global__ void scale_kernel(float* __restrict__ out) {
    int idx = blockIdx.x * 256 + threadIdx.x;
    if (idx >= Bn * 16 * OHW * OHW) return;
    int per_b = 16 * OHW * OHW;
    int b = idx / per_b;
    int p = idx % (OHW * OHW);
    float nrm = g_norm[b * OHW * OHW + p];
    out[idx] *= 0.01f * rsqrtf(nrm + g_stdadd);
}

extern "C" void kernel_launch(void* const* d_in, const int* in_sizes, int n_in,
                              void* d_out, int out_size) {
    const float* x  = (const float*)d_in[0];   // [16,64,256,256]
    const float* z  = (const float*)d_in[1];   // [16,64,32,32]
    const float* fc = (const float*)d_in[2];   // [8,5,2]
    float* out = (float*)d_out;                // [16,16,125,125]

    wgen_kernel<<<16384, 64>>>(z, fc);
    sumsq_kernel<<<4096, 256>>>(x);
    boxnorm_kernel<<<(Bn * OHW * OHW + 255) / 256, 256>>>();
    conv_kernel<<<dim3(2, 16, Bn), 256>>>(x, out);   // 4th launch -> profiled slot
    stats_kernel<<<1, 256>>>();
    scale_kernel<<<(Bn * 16 * OHW * OHW + 255) / 256, 256>>>(out);
}